// round 1
// baseline (speedup 1.0000x reference)
#include <cuda_runtime.h>

#define F    128
#define KN   16
#define H1   64
#define H2   32
#define NC   10
#define WARPS 8
#define THREADS 256

// Dynamic shared layout (61.7 KB -> 3 blocks/SM, 24 warps/SM)
struct Smem {
    float4 W1q[32 * 64];          // [f4][j] : W1q[f4*64+j] = W1[j][4f4..4f4+3]
    float4 rows[WARPS][4][32];    // per-warp 4-row staging buffer
    float  W2t[H1 * H2];          // [j][m]  (transposed for conflict-free reads)
    float  Wct[H2 * NC];          // [m][c]
    float  rbuf[WARPS][H1];
    float  ybuf[WARPS][H2];
};

extern __shared__ unsigned char smem_raw[];

__device__ __forceinline__ float dot4(float4 a, float4 b) {
    return a.x * b.x + a.y * b.y + a.z * b.z + a.w * b.w;
}

__device__ __forceinline__ float warp_sum(float v) {
    #pragma unroll
    for (int o = 16; o > 0; o >>= 1) v += __shfl_xor_sync(0xffffffffu, v, o);
    return v;
}

__global__ __launch_bounds__(THREADS) void gcn_fused_kernel(
    const float* __restrict__ x,
    const float* __restrict__ nb,
    const float* __restrict__ W1,
    const float* __restrict__ W2,
    const float* __restrict__ Wc,
    float* __restrict__ out,
    int n)
{
    Smem& s = *reinterpret_cast<Smem*>(smem_raw);
    const int tid = threadIdx.x;

    // ---- Stage weights into shared ----
    // W1: global [64][128] -> quads [f4][j]
    const float4* W1v = reinterpret_cast<const float4*>(W1);
    #pragma unroll
    for (int t = 0; t < 8; t++) {
        int idx = tid + t * THREADS;          // idx = j*32 + f4
        int j = idx >> 5, f4 = idx & 31;
        s.W1q[f4 * 64 + j] = W1v[idx];
    }
    for (int idx = tid; idx < H1 * H2; idx += THREADS) {
        int m = idx >> 6, j = idx & 63;       // W2 global [32][64]
        s.W2t[j * H2 + m] = W2[idx];
    }
    for (int idx = tid; idx < H2 * NC; idx += THREADS) {
        int c = idx >> 5, m = idx & 31;       // Wc global [10][32]
        s.Wct[m * NC + c] = Wc[idx];
    }
    __syncthreads();

    const int w = tid >> 5, lane = tid & 31;
    const int i = blockIdx.x * WARPS + w;
    if (i >= n) return;

    const float4* xrow  = reinterpret_cast<const float4*>(x  + (size_t)i * F);
    const float4* nbase = reinterpret_cast<const float4*>(nb + (size_t)i * KN * F);

    // ---- Self row: h_x (lane owns outputs j0=lane, j1=lane+32) ----
    float4 v = xrow[lane];
    float ss = warp_sum(dot4(v, v));
    float inv_self = 1.0f / fmaxf(sqrtf(ss), 1e-12f);
    s.rows[w][0][lane] = v;
    __syncwarp();

    float hx0 = 0.f, hx1 = 0.f;
    #pragma unroll
    for (int f4 = 0; f4 < 32; f4++) {
        float4 rv = s.rows[w][0][f4];
        float4 w0 = s.W1q[f4 * 64 + lane];
        float4 w1 = s.W1q[f4 * 64 + lane + 32];
        hx0 += dot4(rv, w0);
        hx1 += dot4(rv, w1);
    }
    hx0 *= inv_self;
    hx1 *= inv_self;

    // ---- Neighbor rows: 4 chunks of 4, accumulate r = sum_k relu(hx + h_k) ----
    float r0 = 0.f, r1 = 0.f;

    #pragma unroll 1
    for (int c = 0; c < 4; c++) {
        __syncwarp();   // rows buffer reuse
        float4 vr[4];
        float  inv[4];
        #pragma unroll
        for (int r = 0; r < 4; r++) vr[r] = nbase[(c * 4 + r) * 32 + lane];
        #pragma unroll
        for (int r = 0; r < 4; r++) {
            float s2 = warp_sum(dot4(vr[r], vr[r]));
            inv[r] = 1.0f / fmaxf(sqrtf(s2), 1e-12f);
            s.rows[w][r][lane] = vr[r];
        }
        __syncwarp();

        float a00 = 0.f, a01 = 0.f, a10 = 0.f, a11 = 0.f;
        float a20 = 0.f, a21 = 0.f, a30 = 0.f, a31 = 0.f;
        #pragma unroll
        for (int f4 = 0; f4 < 32; f4++) {
            float4 w0 = s.W1q[f4 * 64 + lane];
            float4 w1 = s.W1q[f4 * 64 + lane + 32];
            float4 rv0 = s.rows[w][0][f4];
            float4 rv1 = s.rows[w][1][f4];
            float4 rv2 = s.rows[w][2][f4];
            float4 rv3 = s.rows[w][3][f4];
            a00 += dot4(rv0, w0);  a01 += dot4(rv0, w1);
            a10 += dot4(rv1, w0);  a11 += dot4(rv1, w1);
            a20 += dot4(rv2, w0);  a21 += dot4(rv2, w1);
            a30 += dot4(rv3, w0);  a31 += dot4(rv3, w1);
        }
        r0 += fmaxf(hx0 + a00 * inv[0], 0.f) + fmaxf(hx0 + a10 * inv[1], 0.f)
            + fmaxf(hx0 + a20 * inv[2], 0.f) + fmaxf(hx0 + a30 * inv[3], 0.f);
        r1 += fmaxf(hx1 + a01 * inv[0], 0.f) + fmaxf(hx1 + a11 * inv[1], 0.f)
            + fmaxf(hx1 + a21 * inv[2], 0.f) + fmaxf(hx1 + a31 * inv[3], 0.f);
    }

    // ---- Stage 2: y = relu(r @ W2^T)  (lane = m) ----
    s.rbuf[w][lane]      = r0;
    s.rbuf[w][lane + 32] = r1;
    __syncwarp();

    float y = 0.f;
    #pragma unroll
    for (int j = 0; j < H1; j++) y += s.rbuf[w][j] * s.W2t[j * H2 + lane];
    y = fmaxf(y, 0.f);
    s.ybuf[w][lane] = y;
    __syncwarp();

    // ---- Stage 3: out = y @ Wc^T  (lanes 0..9 = c) ----
    if (lane < NC) {
        float o = 0.f;
        #pragma unroll
        for (int m = 0; m < H2; m++) o += s.ybuf[w][m] * s.Wct[m * NC + lane];
        out[(size_t)i * NC + lane] = o;
    }
}

extern "C" void kernel_launch(void* const* d_in, const int* in_sizes, int n_in,
                              void* d_out, int out_size)
{
    const float* x  = (const float*)d_in[0];
    const float* nb = (const float*)d_in[1];
    const float* W1 = (const float*)d_in[2];
    const float* W2 = (const float*)d_in[3];
    const float* Wc = (const float*)d_in[4];
    float* out = (float*)d_out;

    int n = in_sizes[0] / F;
    size_t smem = sizeof(Smem);
    cudaFuncSetAttribute(gcn_fused_kernel,
                         cudaFuncAttributeMaxDynamicSharedMemorySize, (int)smem);
    int grid = (n + WARPS - 1) / WARPS;
    gcn_fused_kernel<<<grid, THREADS, smem>>>(x, nb, W1, W2, Wc, out, n);
}

// round 3
// speedup vs baseline: 1.7937x; 1.7937x over previous
#include <cuda_runtime.h>
#include <cuda_fp16.h>
#include <stdint.h>

#define F    128
#define H1   64
#define H2   32
#define NC   10
#define NPB  7          // nodes per block
#define RV   119        // valid rows = 7*17
#define THREADS 256

// ---- shared memory byte offsets ----
#define SM_AHI  0            // 128x128 fp16 (32KB), swizzled
#define SM_ALO  32768
#define SM_BHI  65536        // 64x128 fp16 (16KB)
#define SM_BLO  81920
#define SM_HB   0            // Hbuf 128x65 f32 (33280) overlays AHI/ALO after GEMM
#define SM_W2T  98304        // 8KB
#define SM_WCT  106496       // 1280
#define SM_RBUF 107776       // 8*64*4
#define SM_YBUF 109824       // 8*32*4
#define SM_TOTAL 110848

// fp16 tile: row stride 256B, 16 chunks of 16B; swizzle chunk ^= (row&7)
static __device__ __forceinline__ uint32_t sw_off(int row, int chunk) {
    return (uint32_t)row * 256u + (uint32_t)((chunk ^ (row & 7)) << 4);
}

static __device__ __forceinline__ uint32_t smem_u32(const void* p) {
    uint32_t a;
    asm("{ .reg .u64 t; cvta.to.shared.u64 t, %1; cvt.u32.u64 %0, t; }" : "=r"(a) : "l"(p));
    return a;
}

static __device__ __forceinline__ void ldsm_x4(uint32_t* r, uint32_t addr) {
    asm volatile("ldmatrix.sync.aligned.m8n8.x4.shared.b16 {%0,%1,%2,%3}, [%4];"
                 : "=r"(r[0]), "=r"(r[1]), "=r"(r[2]), "=r"(r[3]) : "r"(addr));
}

static __device__ __forceinline__ void mma16816(float* c, const uint32_t* a, const uint32_t* b) {
    asm volatile(
        "mma.sync.aligned.m16n8k16.row.col.f32.f16.f16.f32 "
        "{%0,%1,%2,%3}, {%4,%5,%6,%7}, {%8,%9}, {%0,%1,%2,%3};"
        : "+f"(c[0]), "+f"(c[1]), "+f"(c[2]), "+f"(c[3])
        : "r"(a[0]), "r"(a[1]), "r"(a[2]), "r"(a[3]), "r"(b[0]), "r"(b[1]));
}

static __device__ __forceinline__ void cvt_hilo(float v, __half& h, __half& l) {
    h = __float2half_rn(v);
    l = __float2half_rn(v - __half2float(h));
}
static __device__ __forceinline__ uint2 pack4(__half h0, __half h1, __half h2, __half h3) {
    __half2 a = __halves2half2(h0, h1);
    __half2 b = __halves2half2(h2, h3);
    uint2 r;
    r.x = *(const uint32_t*)&a;
    r.y = *(const uint32_t*)&b;
    return r;
}

__global__ __launch_bounds__(THREADS, 2) void gcn_mma_kernel(
    const float* __restrict__ x,  const float* __restrict__ nb,
    const float* __restrict__ W1, const float* __restrict__ W2,
    const float* __restrict__ Wc, float* __restrict__ out, int n)
{
    extern __shared__ char sm[];
    const uint32_t sb = smem_u32(sm);
    const int tid = threadIdx.x, wid = tid >> 5, lane = tid & 31;

    // ---- A-row prefetch: warp w owns rows r = w, w+8, ... (front-batched LDG.128) ----
    float4 q[15];
    const int nr = (RV - 1 - wid) / 8 + 1;
    #pragma unroll
    for (int t = 0; t < 15; t++) {
        q[t] = make_float4(0.f, 0.f, 0.f, 0.f);
        if (t < nr) {
            int r = wid + t * 8;
            int node = r / 17, sub = r - node * 17;
            long gnode = (long)blockIdx.x * NPB + node;
            if (gnode < n) {
                const float4* src = (sub == 0)
                    ? (const float4*)(x + gnode * (long)F)
                    : (const float4*)(nb + (gnode * 16 + (sub - 1)) * (long)F);
                q[t] = src[lane];
            }
        }
    }

    // ---- B tiles: W1 [64][128] -> fp16 hi/lo, swizzled ----
    const float4* W1v = (const float4*)W1;
    #pragma unroll
    for (int t = 0; t < 8; t++) {
        int gi = tid + t * THREADS;        // gi = j*32 + f4
        int j = gi >> 5, f4 = gi & 31;     // f4: quad (4 floats = 8B = half chunk)
        float4 v = W1v[gi];
        __half h0, h1, h2, h3, l0, l1, l2, l3;
        cvt_hilo(v.x, h0, l0); cvt_hilo(v.y, h1, l1);
        cvt_hilo(v.z, h2, l2); cvt_hilo(v.w, h3, l3);
        uint32_t off = sw_off(j, f4 >> 1) + (uint32_t)(f4 & 1) * 8u;
        *(uint2*)(sm + SM_BHI + off) = pack4(h0, h1, h2, h3);
        *(uint2*)(sm + SM_BLO + off) = pack4(l0, l1, l2, l3);
    }

    // ---- small weights: W2^T [j][m], Wc^T [m][c] ----
    for (int i2 = tid; i2 < H1 * H2; i2 += THREADS) {
        int m = i2 >> 6, j = i2 & 63;
        ((float*)(sm + SM_W2T))[j * H2 + m] = W2[i2];
    }
    for (int i2 = tid; i2 < H2 * NC; i2 += THREADS) {
        int c = i2 >> 5, m = i2 & 31;
        ((float*)(sm + SM_WCT))[m * NC + c] = Wc[i2];
    }

    // ---- A: l2-normalize, split fp16 hi/lo, store swizzled ----
    #pragma unroll
    for (int t = 0; t < 15; t++) {
        if (t < nr) {
            int r = wid + t * 8;
            float4 v = q[t];
            float ss = v.x * v.x + v.y * v.y + v.z * v.z + v.w * v.w;
            #pragma unroll
            for (int o = 16; o > 0; o >>= 1) ss += __shfl_xor_sync(0xffffffffu, ss, o);
            float inv = 1.f / fmaxf(sqrtf(ss), 1e-12f);
            __half h0, h1, h2, h3, l0, l1, l2, l3;
            cvt_hilo(v.x * inv, h0, l0); cvt_hilo(v.y * inv, h1, l1);
            cvt_hilo(v.z * inv, h2, l2); cvt_hilo(v.w * inv, h3, l3);
            uint32_t off = sw_off(r, lane >> 1) + (uint32_t)(lane & 1) * 8u;
            *(uint2*)(sm + SM_AHI + off) = pack4(h0, h1, h2, h3);
            *(uint2*)(sm + SM_ALO + off) = pack4(l0, l1, l2, l3);
        }
    }

    // ---- zero padding rows 119..127 (9 rows x 16 chunks, hi & lo) ----
    if (tid < 144) {
        int r = RV + tid / 16, ch = tid & 15;
        uint32_t off = sw_off(r, ch);
        *(uint4*)(sm + SM_AHI + off) = make_uint4(0, 0, 0, 0);
        *(uint4*)(sm + SM_ALO + off) = make_uint4(0, 0, 0, 0);
    }
    __syncthreads();

    // ---- GEMM: warp w computes rows 16w..16w+15 x all 64 cols ----
    // D = Ahi*Bhi^T + Ahi*Blo^T + Alo*Bhi^T (fp32 accum)
    float acc[8][4];
    #pragma unroll
    for (int ntl = 0; ntl < 8; ntl++)
        acc[ntl][0] = acc[ntl][1] = acc[ntl][2] = acc[ntl][3] = 0.f;

    {
        // A ldmatrix address: lanes 0-15 -> rows 16w+0..15 (k-low chunk),
        //                     lanes 16-31 -> same rows (k-high chunk)
        const int arow = 16 * wid + (lane & 15);
        const int asel = lane >> 4;                 // 0: k0-7, 1: k8-15
        // B ldmatrix address (pair p covers n-tiles 2p,2p+1):
        //   n = 16p + ((lane>>4)<<3) + (lane&7),  chunk = kc*2 + ((lane>>3)&1)
        const int bn_local = ((lane >> 4) << 3) + (lane & 7);
        const int bsel = (lane >> 3) & 1;

        #pragma unroll
        for (int kc = 0; kc < 8; kc++) {
            uint32_t ahi[4], alo[4];
            uint32_t aoff = sw_off(arow, kc * 2 + asel);
            ldsm_x4(ahi, sb + SM_AHI + aoff);
            ldsm_x4(alo, sb + SM_ALO + aoff);

            uint32_t bhi[16], blo[16];              // [pair p][4 regs]
            #pragma unroll
            for (int p = 0; p < 4; p++) {
                int bn = 16 * p + bn_local;
                uint32_t boff = sw_off(bn, kc * 2 + bsel);
                ldsm_x4(bhi + p * 4, sb + SM_BHI + boff);
                ldsm_x4(blo + p * 4, sb + SM_BLO + boff);
            }

            #pragma unroll
            for (int ntl = 0; ntl < 8; ntl++) {
                const uint32_t* bh = bhi + (ntl >> 1) * 4 + (ntl & 1) * 2;
                const uint32_t* bl = blo + (ntl >> 1) * 4 + (ntl & 1) * 2;
                mma16816(acc[ntl], ahi, bh);
                mma16816(acc[ntl], ahi, bl);
                mma16816(acc[ntl], alo, bh);
            }
        }
    }
    __syncthreads();   // done reading A/B tiles; Hbuf overlays them

    // ---- write C frags to Hbuf[128][65] ----
    float* hb = (float*)(sm + SM_HB);
    {
        int r0 = 16 * wid + (lane >> 2);
        int c0 = (lane & 3) * 2;
        #pragma unroll
        for (int ntl = 0; ntl < 8; ntl++) {
            int c = ntl * 8 + c0;
            hb[r0 * 65 + c]           = acc[ntl][0];
            hb[r0 * 65 + c + 1]       = acc[ntl][1];
            hb[(r0 + 8) * 65 + c]     = acc[ntl][2];
            hb[(r0 + 8) * 65 + c + 1] = acc[ntl][3];
        }
    }
    __syncthreads();

    // ---- per-node epilogue ----
    long gnode = (long)blockIdx.x * NPB + wid;
    if (wid < NPB && gnode < n) {
        int base = wid * 17;
        float hx0 = hb[base * 65 + lane], hx1 = hb[base * 65 + 32 + lane];
        float r0 = 0.f, r1 = 0.f;
        #pragma unroll
        for (int k = 0; k < 16; k++) {
            const float* hr = hb + (base + 1 + k) * 65;
            r0 += fmaxf(hx0 + hr[lane], 0.f);
            r1 += fmaxf(hx1 + hr[32 + lane], 0.f);
        }
        float* rb = (float*)(sm + SM_RBUF) + wid * 64;
        rb[lane] = r0;
        rb[lane + 32] = r1;
        __syncwarp();
        const float* W2t = (const float*)(sm + SM_W2T);
        float y = 0.f;
        #pragma unroll
        for (int j = 0; j < H1; j++) y += rb[j] * W2t[j * H2 + lane];
        y = fmaxf(y, 0.f);
        float* yb = (float*)(sm + SM_YBUF) + wid * 32;
        yb[lane] = y;
        __syncwarp();
        if (lane < NC) {
            const float* Wct = (const float*)(sm + SM_WCT);
            float o = 0.f;
            #pragma unroll
            for (int m = 0; m < H2; m++) o += yb[m] * Wct[m * NC + lane];
            out[gnode * NC + lane] = o;
        }
    }
}

extern "C" void kernel_launch(void* const* d_in, const int* in_sizes, int n_in,
                              void* d_out, int out_size)
{
    const float* x  = (const float*)d_in[0];
    const float* nb = (const float*)d_in[1];
    const float* W1 = (const float*)d_in[2];
    const float* W2 = (const float*)d_in[3];
    const float* Wc = (const float*)d_in[4];
    float* out = (float*)d_out;

    int n = in_sizes[0] / F;
    cudaFuncSetAttribute(gcn_mma_kernel,
                         cudaFuncAttributeMaxDynamicSharedMemorySize, SM_TOTAL);
    int grid = (n + NPB - 1) / NPB;
    gcn_mma_kernel<<<grid, THREADS, SM_TOTAL>>>(x, nb, W1, W2, Wc, out, n);
}